// round 1
// baseline (speedup 1.0000x reference)
#include <cuda_runtime.h>

// Problem constants (fixed by the reference):
//   B=32, S=1024, V=300, PRETRAIN=300, FLAG=16, ROLE_D=200
//   proj:   [32768, 316] @ [316, 200] -> [32768, 200]
//   scores: per b: [1024, 200] @ [200, 300] (roles^T) -> [1024, 300], col 1 = 0

#define BM 128
#define BN 64
#define BK 8
#define TM 8
#define TN 4
#define NT 256
#define PADA (BM + 4)   // stride 132: 132*4B is 16B-multiple; 132%32==4 -> conflict-free STS
#define PADB (BN + 4)   // stride 68: same properties

// Scratch for the intermediate projection (26.2 MB). Device globals are the
// sanctioned alternative to cudaMalloc under the allocation guards.
__device__ __align__(16) float g_proj[32768 * 200];

// ---------------------------------------------------------------------------
// Kernel 1: proj = concat(pre, wid) @ mat
//   A[m][k] = (k < 300) ? pre[m*300+k] : wid[m*16+(k-300)]   (M=32768, K=316)
//   Bmat[k][n] = mat[k*200+n]                                 (N=200)
// ---------------------------------------------------------------------------
__global__ __launch_bounds__(NT) void proj_kernel(
    const float* __restrict__ pre,
    const float* __restrict__ wid,
    const float* __restrict__ mat)
{
    const int K = 316, N = 200;
    __shared__ __align__(16) float As[BK * PADA];
    __shared__ __align__(16) float Bs[BK * PADB];

    const int tid  = threadIdx.x;
    const int bm   = blockIdx.y * BM;          // M=32768 divisible by BM -> no m guard
    const int bn   = blockIdx.x * BN;
    const int trow = (tid / (BN / TN)) * TM;   // 0..120
    const int tcol = (tid % (BN / TN)) * TN;   // 0..60

    float acc[TM][TN];
    #pragma unroll
    for (int i = 0; i < TM; i++)
        #pragma unroll
        for (int j = 0; j < TN; j++) acc[i][j] = 0.f;

    for (int k0 = 0; k0 < K; k0 += BK) {
        // A tile: 1024 elems, 4 per thread. Coalesced along k (contiguous global).
        #pragma unroll
        for (int j = 0; j < (BM * BK) / NT; j++) {
            int i  = tid + j * NT;
            int ml = i / BK, kk = i % BK;
            int k  = k0 + kk;
            float v = 0.f;
            if (k < 300)      v = pre[(size_t)(bm + ml) * 300 + k];
            else if (k < K)   v = wid[(bm + ml) * 16 + (k - 300)];
            As[kk * PADA + ml] = v;
        }
        // B tile: 512 elems, 2 per thread. mat is [k][n] row-major -> n-fast is coalesced.
        #pragma unroll
        for (int j = 0; j < (BN * BK) / NT; j++) {
            int i  = tid + j * NT;
            int kk = i / BN, nl = i % BN;
            int k  = k0 + kk, n = bn + nl;
            Bs[kk * PADB + nl] = (k < K && n < N) ? mat[k * N + n] : 0.f;
        }
        __syncthreads();

        #pragma unroll
        for (int kk = 0; kk < BK; kk++) {
            float4 a0 = *(const float4*)&As[kk * PADA + trow];
            float4 a1 = *(const float4*)&As[kk * PADA + trow + 4];
            float4 b0 = *(const float4*)&Bs[kk * PADB + tcol];
            float av[TM] = {a0.x, a0.y, a0.z, a0.w, a1.x, a1.y, a1.z, a1.w};
            float bv[TN] = {b0.x, b0.y, b0.z, b0.w};
            #pragma unroll
            for (int i = 0; i < TM; i++)
                #pragma unroll
                for (int j = 0; j < TN; j++)
                    acc[i][j] += av[i] * bv[j];
        }
        __syncthreads();
    }

    #pragma unroll
    for (int i = 0; i < TM; i++) {
        int m = bm + trow + i;
        #pragma unroll
        for (int j = 0; j < TN; j++) {
            int n = bn + tcol + j;
            if (n < N) g_proj[(size_t)m * N + n] = acc[i][j];
        }
    }
}

// ---------------------------------------------------------------------------
// Kernel 2: per-batch scores = proj_b @ roles_b^T, zero column 1
//   A[m][k] = g_proj[(b*1024+m)*200+k]            (M=1024, K=200)
//   Bt[k][n] = roles[b*60000 + n*200 + k]         (N=300)
// ---------------------------------------------------------------------------
__global__ __launch_bounds__(NT) void scores_kernel(
    const float* __restrict__ roles,
    float* __restrict__ out)
{
    const int K = 200, V = 300, SB = 1024;
    __shared__ __align__(16) float As[BK * PADA];
    __shared__ __align__(16) float Bs[BK * PADB];

    const int b    = blockIdx.z;
    const int tid  = threadIdx.x;
    const int bm   = blockIdx.y * BM;          // 1024 divisible by BM
    const int bn   = blockIdx.x * BN;
    const int trow = (tid / (BN / TN)) * TM;
    const int tcol = (tid % (BN / TN)) * TN;

    const float* Ab = g_proj + (size_t)b * SB * K;
    const float* Rb = roles  + (size_t)b * V * K;

    float acc[TM][TN];
    #pragma unroll
    for (int i = 0; i < TM; i++)
        #pragma unroll
        for (int j = 0; j < TN; j++) acc[i][j] = 0.f;

    for (int k0 = 0; k0 < K; k0 += BK) {       // K=200 divisible by BK -> no k guard
        #pragma unroll
        for (int j = 0; j < (BM * BK) / NT; j++) {
            int i  = tid + j * NT;
            int ml = i / BK, kk = i % BK;
            As[kk * PADA + ml] = Ab[(size_t)(bm + ml) * K + (k0 + kk)];
        }
        // roles row-major [n][k] -> k-fast load is coalesced; padded smem kills STS conflicts
        #pragma unroll
        for (int j = 0; j < (BN * BK) / NT; j++) {
            int i  = tid + j * NT;
            int nl = i / BK, kk = i % BK;
            int n  = bn + nl;
            Bs[kk * PADB + nl] = (n < V) ? Rb[(size_t)n * K + (k0 + kk)] : 0.f;
        }
        __syncthreads();

        #pragma unroll
        for (int kk = 0; kk < BK; kk++) {
            float4 a0 = *(const float4*)&As[kk * PADA + trow];
            float4 a1 = *(const float4*)&As[kk * PADA + trow + 4];
            float4 b0 = *(const float4*)&Bs[kk * PADB + tcol];
            float av[TM] = {a0.x, a0.y, a0.z, a0.w, a1.x, a1.y, a1.z, a1.w};
            float bv[TN] = {b0.x, b0.y, b0.z, b0.w};
            #pragma unroll
            for (int i = 0; i < TM; i++)
                #pragma unroll
                for (int j = 0; j < TN; j++)
                    acc[i][j] += av[i] * bv[j];
        }
        __syncthreads();
    }

    #pragma unroll
    for (int i = 0; i < TM; i++) {
        size_t row = (size_t)(b * SB + bm + trow + i) * V;
        #pragma unroll
        for (int j = 0; j < TN; j++) {
            int n = bn + tcol + j;
            if (n < V) out[row + n] = (n == 1) ? 0.f : acc[i][j];
        }
    }
}

// ---------------------------------------------------------------------------
extern "C" void kernel_launch(void* const* d_in, const int* in_sizes, int n_in,
                              void* d_out, int out_size) {
    (void)in_sizes; (void)n_in; (void)out_size;
    const float* roles = (const float*)d_in[0];   // [32, 60000]
    const float* pre   = (const float*)d_in[1];   // [32, 1024, 300]
    const float* wid   = (const float*)d_in[2];   // [32, 1024, 16]
    const float* mat   = (const float*)d_in[3];   // [316, 200]
    float* out = (float*)d_out;                   // [32768, 300]

    dim3 g1((200 + BN - 1) / BN, 32768 / BM);     // (4, 256)
    proj_kernel<<<g1, NT>>>(pre, wid, mat);

    dim3 g2((300 + BN - 1) / BN, 1024 / BM, 32);  // (5, 8, 32)
    scores_kernel<<<g2, NT>>>(roles, out);
}

// round 2
// speedup vs baseline: 1.2770x; 1.2770x over previous
#include <cuda_runtime.h>
#include <cstdint>

// Problem constants:
//   B=32, S=1024, V=300, PRETRAIN=300, FLAG=16, ROLE_D=200
//   proj:   [32768, 316] @ [316, 200] -> [32768, 200]
//   scores: per b: [1024, 200] @ roles_b^T [200, 300] -> [1024, 300], col1=0

#define NT   128
#define BM   128
#define BN   64
#define BK   16
#define TM   8
#define TN   8
#define PADA 132   // 132*4B = 528 = 16B-mult; 132%32==4 -> scatter-friendly
#define PADB 68    // 68*4B  = 272 = 16B-mult

// 26.2 MB scratch for the intermediate projection (device global: alloc-guard safe)
__device__ __align__(16) float g_proj[32768 * 200];

// ---- packed fp32x2 helpers (FFMA2 path; ptxas never emits this from C++) ----
__device__ __forceinline__ unsigned long long pack_dup(float a) {
    unsigned long long r;
    unsigned int u = __float_as_uint(a);
    asm("mov.b64 %0, {%1, %1};" : "=l"(r) : "r"(u));
    return r;
}
__device__ __forceinline__ void ffma2(unsigned long long& acc,
                                      unsigned long long a2,
                                      unsigned long long b2) {
    asm("fma.rn.f32x2 %0, %1, %2, %0;" : "+l"(acc) : "l"(a2), "l"(b2));
}
__device__ __forceinline__ float lo32(unsigned long long v) {
    return __uint_as_float((unsigned int)(v & 0xffffffffull));
}
__device__ __forceinline__ float hi32(unsigned long long v) {
    return __uint_as_float((unsigned int)(v >> 32));
}

// Shared inner product step: 2 LDS.128 (A) + 2 LDS.128 (B, as b64 pairs) +
// 8 broadcast packs + 32 FFMA2  => 64 FMAs in ~44 issue slots.
#define COMPUTE_KSTEP(kk)                                                      \
    {                                                                          \
        float4 a0 = *(const float4*)&As[(kk) * PADA + trow];                   \
        float4 a1 = *(const float4*)&As[(kk) * PADA + trow + 4];               \
        ulonglong2 b01 = *(const ulonglong2*)&Bs[(kk) * PADB + tcol];          \
        ulonglong2 b23 = *(const ulonglong2*)&Bs[(kk) * PADB + tcol + 4];      \
        float av[TM] = {a0.x, a0.y, a0.z, a0.w, a1.x, a1.y, a1.z, a1.w};       \
        unsigned long long bp[4] = {b01.x, b01.y, b23.x, b23.y};               \
        _Pragma("unroll")                                                      \
        for (int i = 0; i < TM; i++) {                                         \
            unsigned long long a2 = pack_dup(av[i]);                           \
            _Pragma("unroll")                                                  \
            for (int j = 0; j < 4; j++) ffma2(acc[i][j], a2, bp[j]);           \
        }                                                                      \
    }

// ---------------------------------------------------------------------------
// Kernel 1: proj = concat(pre, wid) @ mat      (M=32768, K=316, N=200)
// ---------------------------------------------------------------------------
__global__ __launch_bounds__(NT) void proj_kernel(
    const float* __restrict__ pre,
    const float* __restrict__ wid,
    const float* __restrict__ mat)
{
    const int K = 316, N = 200;
    __shared__ __align__(16) float As[BK * PADA];
    __shared__ __align__(16) float Bs[BK * PADB];

    const int tid  = threadIdx.x;
    const int bm   = blockIdx.y * BM;
    const int bn   = blockIdx.x * BN;
    const int trow = (tid / (BN / TN)) * TM;   // (tid/8)*8
    const int tcol = (tid % (BN / TN)) * TN;   // (tid%8)*8

    unsigned long long acc[TM][4];
    #pragma unroll
    for (int i = 0; i < TM; i++)
        #pragma unroll
        for (int j = 0; j < 4; j++) acc[i][j] = 0ull;

    for (int k0 = 0; k0 < K; k0 += BK) {
        // A tile: 128x16 -> 512 float4 chunks, 4/thread, transposed scatter.
        // Chunk boundaries (4-aligned) never straddle the 300/316 splits.
        #pragma unroll
        for (int t = 0; t < 4; t++) {
            int idx = tid + t * NT;
            int ml = idx / 4, kq = idx % 4;
            int k  = k0 + kq * 4;
            float4 v = make_float4(0.f, 0.f, 0.f, 0.f);
            if (k < 300)      v = *(const float4*)&pre[(size_t)(bm + ml) * 300 + k];
            else if (k < K)   v = *(const float4*)&wid[(bm + ml) * 16 + (k - 300)];
            As[(kq * 4 + 0) * PADA + ml] = v.x;
            As[(kq * 4 + 1) * PADA + ml] = v.y;
            As[(kq * 4 + 2) * PADA + ml] = v.z;
            As[(kq * 4 + 3) * PADA + ml] = v.w;
        }
        // B tile: 16x64 direct copy (mat is [k][n], n-fast = coalesced).
        #pragma unroll
        for (int t = 0; t < 2; t++) {
            int idx = tid + t * NT;
            int kk = idx / 16, nq = idx % 16;
            int k  = k0 + kk;
            int n  = bn + nq * 4;
            float4 v = make_float4(0.f, 0.f, 0.f, 0.f);
            if (k < K) {
                if (n + 3 < N) {
                    v = *(const float4*)&mat[k * N + n];
                } else {
                    if (n + 0 < N) v.x = mat[k * N + n + 0];
                    if (n + 1 < N) v.y = mat[k * N + n + 1];
                    if (n + 2 < N) v.z = mat[k * N + n + 2];
                    if (n + 3 < N) v.w = mat[k * N + n + 3];
                }
            }
            *(float4*)&Bs[kk * PADB + nq * 4] = v;
        }
        __syncthreads();

        #pragma unroll
        for (int kk = 0; kk < BK; kk++) COMPUTE_KSTEP(kk)
        __syncthreads();
    }

    #pragma unroll
    for (int i = 0; i < TM; i++) {
        size_t row = (size_t)(bm + trow + i) * N;
        #pragma unroll
        for (int j = 0; j < 4; j++) {
            int n = bn + tcol + 2 * j;
            if (n + 0 < N) g_proj[row + n + 0] = lo32(acc[i][j]);
            if (n + 1 < N) g_proj[row + n + 1] = hi32(acc[i][j]);
        }
    }
}

// ---------------------------------------------------------------------------
// Kernel 2: per-batch scores = proj_b @ roles_b^T, zero col 1
//           (M=1024/batch, K=200, N=300)
// ---------------------------------------------------------------------------
__global__ __launch_bounds__(NT) void scores_kernel(
    const float* __restrict__ roles,
    float* __restrict__ out)
{
    const int K = 200, V = 300, SB = 1024;
    __shared__ __align__(16) float As[BK * PADA];
    __shared__ __align__(16) float Bs[BK * PADB];

    const int b    = blockIdx.z;
    const int tid  = threadIdx.x;
    const int bm   = blockIdx.y * BM;
    const int bn   = blockIdx.x * BN;
    const int trow = (tid / (BN / TN)) * TM;
    const int tcol = (tid % (BN / TN)) * TN;

    const float* Ab = g_proj + (size_t)b * SB * K;
    const float* Rb = roles  + (size_t)b * V * K;

    unsigned long long acc[TM][4];
    #pragma unroll
    for (int i = 0; i < TM; i++)
        #pragma unroll
        for (int j = 0; j < 4; j++) acc[i][j] = 0ull;

    for (int k0 = 0; k0 < K; k0 += BK) {
        // A tile: rows of g_proj (contiguous k), transposed scatter into As.
        #pragma unroll
        for (int t = 0; t < 4; t++) {
            int idx = tid + t * NT;
            int ml = idx / 4, kq = idx % 4;
            int k  = k0 + kq * 4;
            float4 v = make_float4(0.f, 0.f, 0.f, 0.f);
            if (k < K) v = *(const float4*)&Ab[(size_t)(bm + ml) * K + k];
            As[(kq * 4 + 0) * PADA + ml] = v.x;
            As[(kq * 4 + 1) * PADA + ml] = v.y;
            As[(kq * 4 + 2) * PADA + ml] = v.z;
            As[(kq * 4 + 3) * PADA + ml] = v.w;
        }
        // B tile: roles rows (contiguous k), transposed scatter into Bs.
        #pragma unroll
        for (int t = 0; t < 2; t++) {
            int idx = tid + t * NT;
            int nl = idx / 4, kq = idx % 4;
            int k  = k0 + kq * 4;
            int n  = bn + nl;
            float4 v = make_float4(0.f, 0.f, 0.f, 0.f);
            if (n < V && k < K) v = *(const float4*)&Rb[(size_t)n * K + k];
            Bs[(kq * 4 + 0) * PADB + nl] = v.x;
            Bs[(kq * 4 + 1) * PADB + nl] = v.y;
            Bs[(kq * 4 + 2) * PADB + nl] = v.z;
            Bs[(kq * 4 + 3) * PADB + nl] = v.w;
        }
        __syncthreads();

        #pragma unroll
        for (int kk = 0; kk < BK; kk++) COMPUTE_KSTEP(kk)
        __syncthreads();
    }

    #pragma unroll
    for (int i = 0; i < TM; i++) {
        size_t row = (size_t)(b * SB + bm + trow + i) * V;
        #pragma unroll
        for (int j = 0; j < 4; j++) {
            int n = bn + tcol + 2 * j;
            float vlo = lo32(acc[i][j]);
            float vhi = hi32(acc[i][j]);
            if (n + 0 < V) out[row + n + 0] = (n + 0 == 1) ? 0.f : vlo;
            if (n + 1 < V) out[row + n + 1] = (n + 1 == 1) ? 0.f : vhi;
        }
    }
}

// ---------------------------------------------------------------------------
extern "C" void kernel_launch(void* const* d_in, const int* in_sizes, int n_in,
                              void* d_out, int out_size) {
    (void)in_sizes; (void)n_in; (void)out_size;
    const float* roles = (const float*)d_in[0];   // [32, 60000]
    const float* pre   = (const float*)d_in[1];   // [32, 1024, 300]
    const float* wid   = (const float*)d_in[2];   // [32, 1024, 16]
    const float* mat   = (const float*)d_in[3];   // [316, 200]
    float* out = (float*)d_out;                   // [32768, 300]

    dim3 g1((200 + BN - 1) / BN, 32768 / BM);     // (4, 256)
    proj_kernel<<<g1, NT>>>(pre, wid, mat);

    dim3 g2((300 + BN - 1) / BN, 1024 / BM, 32);  // (5, 8, 32)
    scores_kernel<<<g2, NT>>>(roles, out);
}

// round 4
// speedup vs baseline: 3.1731x; 2.4848x over previous
#include <cuda_runtime.h>
#include <cuda_bf16.h>
#include <cstdint>

// B=32, S=1024, V=300, PRETRAIN=300, FLAG=16, ROLE_D=200
// Stage 1: proj[32768,200] = concat(pre,wid)[32768,316] @ matrix[316,200]
// Stage 2: out[b,1024,300] = proj_b @ roles_b^T, col 1 = 0
//
// Split-bf16 (hi+lo) GEMMs on the tensor pipe via mma.sync (plain sm_100-legal
// PTX; tcgen05 needs sm_100a which this toolchain doesn't target).
//   a=ah+al, b=bh+bl;  a*b ~= ah*bh + al*bh + ah*bl   (rel err ~2^-16)
// All operands K-major, zero-padded (K 316->320 / 200->256, V 300->320,
// N 200->256) so the mainloop is guard-free.

// ------------------------------ scratch -------------------------------------
__device__ __align__(16) __nv_bfloat16 g_a1h[32768 * 320];
__device__ __align__(16) __nv_bfloat16 g_a1l[32768 * 320];
__device__ __align__(16) __nv_bfloat16 g_b1h[256 * 320];
__device__ __align__(16) __nv_bfloat16 g_b1l[256 * 320];
__device__ __align__(16) __nv_bfloat16 g_ph [32768 * 256];
__device__ __align__(16) __nv_bfloat16 g_pl [32768 * 256];
__device__ __align__(16) __nv_bfloat16 g_rlh[32 * 320 * 256];
__device__ __align__(16) __nv_bfloat16 g_rll[32 * 320 * 256];

// ------------------------------ helpers -------------------------------------
__device__ __forceinline__ uint32_t smem_u32(const void* p) {
    uint32_t a;
    asm("{ .reg .u64 t; cvta.to.shared.u64 t, %1; cvt.u32.u64 %0, t; }"
        : "=r"(a) : "l"(p));
    return a;
}
__device__ __forceinline__ void cpa16(uint32_t dst, const void* src) {
    asm volatile("cp.async.cg.shared.global [%0], [%1], 16;"
                 :: "r"(dst), "l"(src) : "memory");
}
#define CP_COMMIT() asm volatile("cp.async.commit_group;" ::: "memory")
#define LDM_X4(r, addr)                                                        \
    asm volatile("ldmatrix.sync.aligned.m8n8.x4.shared.b16 {%0,%1,%2,%3}, [%4];" \
        : "=r"((r)[0]), "=r"((r)[1]), "=r"((r)[2]), "=r"((r)[3]) : "r"(addr))
#define MMA_BF16(d, a, b)                                                      \
    asm volatile("mma.sync.aligned.m16n8k16.row.col.f32.bf16.bf16.f32 "        \
        "{%0,%1,%2,%3}, {%4,%5,%6,%7}, {%8,%9}, {%0,%1,%2,%3};"                \
        : "+f"((d)[0]), "+f"((d)[1]), "+f"((d)[2]), "+f"((d)[3])               \
        : "r"((a)[0]), "r"((a)[1]), "r"((a)[2]), "r"((a)[3]),                  \
          "r"((b)[0]), "r"((b)[1]))

// conflict-free swizzle for 64B rows (4x16B chunks): 8 consecutive rows cover
// 8 distinct 16B granules of a 128B window.
__device__ __forceinline__ uint32_t swz(int r, int c) {
    return (uint32_t)(r * 64 + ((c ^ ((r >> 1) & 3)) << 4));
}

__device__ __forceinline__ void split2(float x, float y, uint32_t& h, uint32_t& l) {
    __nv_bfloat16 h0 = __float2bfloat16_rn(x);
    __nv_bfloat16 h1 = __float2bfloat16_rn(y);
    __nv_bfloat16 l0 = __float2bfloat16_rn(x - __bfloat162float(h0));
    __nv_bfloat16 l1 = __float2bfloat16_rn(y - __bfloat162float(h1));
    __nv_bfloat162 hp; hp.x = h0; hp.y = h1;
    __nv_bfloat162 lp; lp.x = l0; lp.y = l1;
    h = *(uint32_t*)&hp; l = *(uint32_t*)&lp;
}

// ------------------------------ prep kernels --------------------------------
__device__ __forceinline__ void split_store(__nv_bfloat16* H, __nv_bfloat16* L,
                                            size_t idx2, float2 v) {
    uint32_t h, l; split2(v.x, v.y, h, l);
    ((uint32_t*)H)[idx2] = h; ((uint32_t*)L)[idx2] = l;
}

__global__ void prep_a1(const float* __restrict__ pre, const float* __restrict__ wid) {
    int idx = blockIdx.x * blockDim.x + threadIdx.x;   // 32768*160
    if (idx >= 32768 * 160) return;
    int m = idx / 160, kp = idx % 160, k = kp * 2;
    float2 v = make_float2(0.f, 0.f);
    if (k < 300)        v = *(const float2*)&pre[(size_t)m * 300 + k];
    else if (k < 316)   v = *(const float2*)&wid[m * 16 + (k - 300)];
    split_store(g_a1h, g_a1l, (size_t)m * 160 + kp, v);
}

__global__ void prep_b1(const float* __restrict__ mat) {
    int idx = blockIdx.x * blockDim.x + threadIdx.x;   // 256*160
    if (idx >= 256 * 160) return;
    int n = idx / 160, kp = idx % 160, k = kp * 2;
    float2 v = make_float2(0.f, 0.f);
    if (n < 200) {
        if (k     < 316) v.x = mat[(k    ) * 200 + n];
        if (k + 1 < 316) v.y = mat[(k + 1) * 200 + n];
    }
    split_store(g_b1h, g_b1l, (size_t)n * 160 + kp, v);
}

__global__ void prep_roles(const float* __restrict__ roles) {
    int idx = blockIdx.x * blockDim.x + threadIdx.x;   // 32*320*128
    if (idx >= 32 * 320 * 128) return;
    int kp = idx % 128, t = idx / 128;
    int v_ = t % 320, b = t / 320;
    int k = kp * 2;
    float2 v = make_float2(0.f, 0.f);
    if (v_ < 300 && k < 200)
        v = *(const float2*)&roles[(size_t)b * 60000 + (size_t)v_ * 200 + k];
    split_store(g_rlh, g_rll, (size_t)(b * 320 + v_) * 128 + kp, v);
}

// ------------------------------ GEMM kernel ---------------------------------
// CTA 128x64 tile, 8 warps (4 m x 2 n), warp tile 32x32, K-chunk 32.
// smem buffer: Ah[8K] Al[8K] Bh[4K] Bl[4K] = 24KB, double-buffered = 48KB.
#define OFF_AH 0
#define OFF_AL 8192
#define OFF_BH 16384
#define OFF_BL 20480
#define BUFB   24576

template <int KSTR_A, int KSTR_B, int KC, bool SCORES>
__global__ void __launch_bounds__(256) gemm_wmma(
    const __nv_bfloat16* __restrict__ Agh, const __nv_bfloat16* __restrict__ Agl,
    const __nv_bfloat16* __restrict__ Bgh, const __nv_bfloat16* __restrict__ Bgl,
    float* __restrict__ outF,
    __nv_bfloat16* __restrict__ Ph, __nv_bfloat16* __restrict__ Pl)
{
    __shared__ __align__(16) char sm[2][BUFB];
    const uint32_t sb = smem_u32(sm);
    const int tid = threadIdx.x, w = tid >> 5, lane = tid & 31;
    const int wm = w & 3, wn = w >> 2;
    const int bm = blockIdx.y * 128, bn = blockIdx.x * 64, bz = blockIdx.z;

    const __nv_bfloat16 *Abh, *Abl, *Bbh, *Bbl;
    if (SCORES) {
        size_t ao = ((size_t)bz * 1024 + bm) * KSTR_A;
        size_t bo = ((size_t)bz * 320 + bn) * KSTR_B;
        Abh = Agh + ao; Abl = Agl + ao; Bbh = Bgh + bo; Bbl = Bgl + bo;
    } else {
        Abh = Agh + (size_t)bm * KSTR_A; Abl = Agl + (size_t)bm * KSTR_A;
        Bbh = Bgh + (size_t)bn * KSTR_B; Bbl = Bgl + (size_t)bn * KSTR_B;
    }

    float acc[2][4][4];
    #pragma unroll
    for (int i = 0; i < 2; i++)
        #pragma unroll
        for (int j = 0; j < 4; j++)
            #pragma unroll
            for (int e = 0; e < 4; e++) acc[i][j][e] = 0.f;

    // ---- async tile loader (A: 512 x16B per array, B: 256 x16B per array)
    #define LOAD_TILES(kc)                                                     \
    {                                                                          \
        const uint32_t base = sb + ((kc) & 1) * BUFB;                          \
        const int ko = (kc) * 32;                                              \
        _Pragma("unroll")                                                      \
        for (int it = 0; it < 2; it++) {                                       \
            int idx = tid + it * 256;                                          \
            int r = idx >> 2, c = idx & 3;                                     \
            uint32_t o = swz(r, c);                                            \
            const char* sh = (const char*)(Abh + (size_t)r * KSTR_A + ko) + c * 16; \
            const char* sl = (const char*)(Abl + (size_t)r * KSTR_A + ko) + c * 16; \
            cpa16(base + OFF_AH + o, sh);                                      \
            cpa16(base + OFF_AL + o, sl);                                      \
        }                                                                      \
        {                                                                      \
            int r = tid >> 2, c = tid & 3;                                     \
            uint32_t o = swz(r, c);                                            \
            const char* sh = (const char*)(Bbh + (size_t)r * KSTR_B + ko) + c * 16; \
            const char* sl = (const char*)(Bbl + (size_t)r * KSTR_B + ko) + c * 16; \
            cpa16(base + OFF_BH + o, sh);                                      \
            cpa16(base + OFF_BL + o, sl);                                      \
        }                                                                      \
        CP_COMMIT();                                                           \
    }

    LOAD_TILES(0);

    #pragma unroll 1
    for (int kc = 0; kc < KC; kc++) {
        if (kc + 1 < KC) {
            LOAD_TILES(kc + 1);
            asm volatile("cp.async.wait_group 1;" ::: "memory");
        } else {
            asm volatile("cp.async.wait_group 0;" ::: "memory");
        }
        __syncthreads();

        const uint32_t base = sb + (kc & 1) * BUFB;
        #pragma unroll
        for (int kk = 0; kk < 2; kk++) {
            uint32_t ah[2][4], al[2][4], bh[4][2], bl[4][2];
            #pragma unroll
            for (int i = 0; i < 2; i++) {
                int row = wm * 32 + i * 16 + (lane & 15);
                int ci  = kk * 2 + (lane >> 4);
                uint32_t ad = base + OFF_AH + swz(row, ci);
                LDM_X4(ah[i], ad);
                LDM_X4(al[i], ad + (OFF_AL - OFF_AH));
            }
            #pragma unroll
            for (int jj = 0; jj < 2; jj++) {
                int row = wn * 32 + jj * 16 + ((lane >> 4) << 3) + (lane & 7);
                int ci  = kk * 2 + ((lane >> 3) & 1);
                uint32_t bd = base + OFF_BH + swz(row, ci);
                uint32_t t[4];
                LDM_X4(t, bd);
                bh[jj*2][0] = t[0]; bh[jj*2][1] = t[1];
                bh[jj*2+1][0] = t[2]; bh[jj*2+1][1] = t[3];
                LDM_X4(t, bd + (OFF_BL - OFF_BH));
                bl[jj*2][0] = t[0]; bl[jj*2][1] = t[1];
                bl[jj*2+1][0] = t[2]; bl[jj*2+1][1] = t[3];
            }
            #pragma unroll
            for (int i = 0; i < 2; i++)
                #pragma unroll
                for (int j = 0; j < 4; j++) MMA_BF16(acc[i][j], ah[i], bh[j]);
            #pragma unroll
            for (int i = 0; i < 2; i++)
                #pragma unroll
                for (int j = 0; j < 4; j++) MMA_BF16(acc[i][j], al[i], bh[j]);
            #pragma unroll
            for (int i = 0; i < 2; i++)
                #pragma unroll
                for (int j = 0; j < 4; j++) MMA_BF16(acc[i][j], ah[i], bl[j]);
        }
        __syncthreads();
    }

    // ---- epilogue: thread owns rows r0, r0+8 x cols col, col+1 per (i,j)
    #pragma unroll
    for (int i = 0; i < 2; i++) {
        int r0 = bm + wm * 32 + i * 16 + (lane >> 2);
        #pragma unroll
        for (int j = 0; j < 4; j++) {
            int col = bn + wn * 32 + j * 8 + (lane & 3) * 2;
            if (SCORES) {
                if (col < 300) {
                    size_t g0 = ((size_t)bz * 1024 + r0) * 300 + col;
                    size_t g1 = g0 + 8 * 300;
                    float2 v0 = make_float2(acc[i][j][0],
                                            (col == 0) ? 0.f : acc[i][j][1]);
                    float2 v1 = make_float2(acc[i][j][2],
                                            (col == 0) ? 0.f : acc[i][j][3]);
                    *(float2*)&outF[g0] = v0;
                    *(float2*)&outF[g1] = v1;
                }
            } else {
                uint32_t h, l;
                size_t p0 = (size_t)r0 * 256 + col;
                split2(acc[i][j][0], acc[i][j][1], h, l);
                *(uint32_t*)&Ph[p0] = h; *(uint32_t*)&Pl[p0] = l;
                size_t p1 = p0 + (size_t)8 * 256;
                split2(acc[i][j][2], acc[i][j][3], h, l);
                *(uint32_t*)&Ph[p1] = h; *(uint32_t*)&Pl[p1] = l;
            }
        }
    }
    #undef LOAD_TILES
}

// ------------------------------ launch --------------------------------------
extern "C" void kernel_launch(void* const* d_in, const int* in_sizes, int n_in,
                              void* d_out, int out_size) {
    (void)in_sizes; (void)n_in; (void)out_size;
    const float* roles = (const float*)d_in[0];   // [32, 60000]
    const float* pre   = (const float*)d_in[1];   // [32, 1024, 300]
    const float* wid   = (const float*)d_in[2];   // [32, 1024, 16]
    const float* mat   = (const float*)d_in[3];   // [316, 200]
    float* out = (float*)d_out;                   // [32768, 300]

    __nv_bfloat16 *a1h, *a1l, *b1h, *b1l, *ph, *pl, *rlh, *rll;
    cudaGetSymbolAddress((void**)&a1h, g_a1h);
    cudaGetSymbolAddress((void**)&a1l, g_a1l);
    cudaGetSymbolAddress((void**)&b1h, g_b1h);
    cudaGetSymbolAddress((void**)&b1l, g_b1l);
    cudaGetSymbolAddress((void**)&ph,  g_ph);
    cudaGetSymbolAddress((void**)&pl,  g_pl);
    cudaGetSymbolAddress((void**)&rlh, g_rlh);
    cudaGetSymbolAddress((void**)&rll, g_rll);

    prep_a1   <<<(32768 * 160 + 255) / 256, 256>>>(pre, wid);
    prep_b1   <<<(256 * 160 + 255) / 256, 256>>>(mat);
    prep_roles<<<(32 * 320 * 128 + 255) / 256, 256>>>(roles);

    // proj: [32768,320] @ b1^T -> g_ph/g_pl (4 n-tiles x 256 m-tiles)
    gemm_wmma<320, 320, 10, false><<<dim3(4, 256, 1), 256>>>(
        a1h, a1l, b1h, b1l, nullptr, ph, pl);

    // scores: per-batch proj_b @ roles_b^T -> out (5 n-tiles x 8 m-tiles x 32 b)
    gemm_wmma<256, 256, 8, true><<<dim3(5, 8, 32), 256>>>(
        ph, pl, rlh, rll, out, nullptr, nullptr);
}

// round 5
// speedup vs baseline: 3.3533x; 1.0568x over previous
#include <cuda_runtime.h>
#include <cuda_bf16.h>
#include <cstdint>

// B=32, S=1024, V=300, PRETRAIN=300, FLAG=16, ROLE_D=200
// Stage 1: proj[32768,200] = concat(pre,wid)[32768,316] @ matrix[316,200]
// Stage 2: out[b,1024,300] = proj_b @ roles_b^T, col 1 = 0
//
// Split-bf16 (hi+lo) GEMMs on the tensor pipe via mma.sync.
//   a=ah+al, b=bh+bl;  a*b ~= ah*bh + al*bh + ah*bl   (rel err ~1e-5)
// K pads: stage1 316->320, stage2 200->224. N pads: 200->256, V 300->320.
// 3-stage cp.async pipeline, one __syncthreads per 32-K chunk.

// ------------------------------ scratch -------------------------------------
__device__ __align__(16) __nv_bfloat16 g_a1h[32768 * 320];
__device__ __align__(16) __nv_bfloat16 g_a1l[32768 * 320];
__device__ __align__(16) __nv_bfloat16 g_b1h[256 * 320];
__device__ __align__(16) __nv_bfloat16 g_b1l[256 * 320];
__device__ __align__(16) __nv_bfloat16 g_ph [32768 * 224];
__device__ __align__(16) __nv_bfloat16 g_pl [32768 * 224];
__device__ __align__(16) __nv_bfloat16 g_rlh[32 * 320 * 224];
__device__ __align__(16) __nv_bfloat16 g_rll[32 * 320 * 224];

// ------------------------------ helpers -------------------------------------
__device__ __forceinline__ uint32_t smem_u32(const void* p) {
    uint32_t a;
    asm("{ .reg .u64 t; cvta.to.shared.u64 t, %1; cvt.u32.u64 %0, t; }"
        : "=r"(a) : "l"(p));
    return a;
}
__device__ __forceinline__ void cpa16(uint32_t dst, const void* src) {
    asm volatile("cp.async.cg.shared.global [%0], [%1], 16;"
                 :: "r"(dst), "l"(src) : "memory");
}
#define CP_COMMIT() asm volatile("cp.async.commit_group;" ::: "memory")
#define LDM_X4(r, addr)                                                        \
    asm volatile("ldmatrix.sync.aligned.m8n8.x4.shared.b16 {%0,%1,%2,%3}, [%4];" \
        : "=r"((r)[0]), "=r"((r)[1]), "=r"((r)[2]), "=r"((r)[3]) : "r"(addr))
#define MMA_BF16(d, a, b)                                                      \
    asm volatile("mma.sync.aligned.m16n8k16.row.col.f32.bf16.bf16.f32 "        \
        "{%0,%1,%2,%3}, {%4,%5,%6,%7}, {%8,%9}, {%0,%1,%2,%3};"                \
        : "+f"((d)[0]), "+f"((d)[1]), "+f"((d)[2]), "+f"((d)[3])               \
        : "r"((a)[0]), "r"((a)[1]), "r"((a)[2]), "r"((a)[3]),                  \
          "r"((b)[0]), "r"((b)[1]))

// conflict-free swizzle for 64B rows (4x16B chunks)
__device__ __forceinline__ uint32_t swz(int r, int c) {
    return (uint32_t)(r * 64 + ((c ^ ((r >> 1) & 3)) << 4));
}

__device__ __forceinline__ void split2(float x, float y, uint32_t& h, uint32_t& l) {
    __nv_bfloat16 h0 = __float2bfloat16_rn(x);
    __nv_bfloat16 h1 = __float2bfloat16_rn(y);
    __nv_bfloat16 l0 = __float2bfloat16_rn(x - __bfloat162float(h0));
    __nv_bfloat16 l1 = __float2bfloat16_rn(y - __bfloat162float(h1));
    __nv_bfloat162 hp; hp.x = h0; hp.y = h1;
    __nv_bfloat162 lp; lp.x = l0; lp.y = l1;
    h = *(uint32_t*)&hp; l = *(uint32_t*)&lp;
}

// ------------------------------ prep kernels --------------------------------
__device__ __forceinline__ void split_store(__nv_bfloat16* H, __nv_bfloat16* L,
                                            size_t idx2, float2 v) {
    uint32_t h, l; split2(v.x, v.y, h, l);
    ((uint32_t*)H)[idx2] = h; ((uint32_t*)L)[idx2] = l;
}

__global__ void prep_a1(const float* __restrict__ pre, const float* __restrict__ wid) {
    int idx = blockIdx.x * blockDim.x + threadIdx.x;   // 32768*160
    if (idx >= 32768 * 160) return;
    int m = idx / 160, kp = idx % 160, k = kp * 2;
    float2 v = make_float2(0.f, 0.f);
    if (k < 300)        v = *(const float2*)&pre[(size_t)m * 300 + k];
    else if (k < 316)   v = *(const float2*)&wid[m * 16 + (k - 300)];
    split_store(g_a1h, g_a1l, (size_t)m * 160 + kp, v);
}

__global__ void prep_b1(const float* __restrict__ mat) {
    int idx = blockIdx.x * blockDim.x + threadIdx.x;   // 256*160
    if (idx >= 256 * 160) return;
    int n = idx / 160, kp = idx % 160, k = kp * 2;
    float2 v = make_float2(0.f, 0.f);
    if (n < 200) {
        if (k     < 316) v.x = mat[(k    ) * 200 + n];
        if (k + 1 < 316) v.y = mat[(k + 1) * 200 + n];
    }
    split_store(g_b1h, g_b1l, (size_t)n * 160 + kp, v);
}

__global__ void prep_roles(const float* __restrict__ roles) {
    int idx = blockIdx.x * blockDim.x + threadIdx.x;   // 32*320*112
    if (idx >= 32 * 320 * 112) return;
    int kp = idx % 112, t = idx / 112;
    int v_ = t % 320, b = t / 320;
    int k = kp * 2;
    float2 v = make_float2(0.f, 0.f);
    if (v_ < 300 && k < 200)
        v = *(const float2*)&roles[(size_t)b * 60000 + (size_t)v_ * 200 + k];
    split_store(g_rlh, g_rll, (size_t)(b * 320 + v_) * 112 + kp, v);
}

// ------------------------------ GEMM kernel ---------------------------------
// CTA 128x64, 8 warps (4m x 2n), warp tile 32x32, K-chunk 32, 3-stage pipeline.
// buffer: Ah[8K] Al[8K] Bh[4K] Bl[4K] = 24KB; 3 stages = 72KB dynamic smem.
#define OFF_AH 0
#define OFF_AL 8192
#define OFF_BH 16384
#define OFF_BL 20480
#define BUFB   24576
#define NSTAGE 3
#define SMEM_TOTAL (NSTAGE * BUFB)

template <int KSTR_A, int KSTR_B, int KC, bool SCORES>
__global__ void __launch_bounds__(256) gemm_wmma(
    const __nv_bfloat16* __restrict__ Agh, const __nv_bfloat16* __restrict__ Agl,
    const __nv_bfloat16* __restrict__ Bgh, const __nv_bfloat16* __restrict__ Bgl,
    float* __restrict__ outF,
    __nv_bfloat16* __restrict__ Ph, __nv_bfloat16* __restrict__ Pl)
{
    extern __shared__ __align__(16) char smem_dyn[];
    const uint32_t sb = smem_u32(smem_dyn);
    const int tid = threadIdx.x, w = tid >> 5, lane = tid & 31;
    const int wm = w & 3, wn = w >> 2;
    const int bm = blockIdx.y * 128, bn = blockIdx.x * 64, bz = blockIdx.z;

    const __nv_bfloat16 *Abh, *Abl, *Bbh, *Bbl;
    if (SCORES) {
        size_t ao = ((size_t)bz * 1024 + bm) * KSTR_A;
        size_t bo = ((size_t)bz * 320 + bn) * KSTR_B;
        Abh = Agh + ao; Abl = Agl + ao; Bbh = Bgh + bo; Bbl = Bgl + bo;
    } else {
        Abh = Agh + (size_t)bm * KSTR_A; Abl = Agl + (size_t)bm * KSTR_A;
        Bbh = Bgh + (size_t)bn * KSTR_B; Bbl = Bgl + (size_t)bn * KSTR_B;
    }

    float acc[2][4][4];
    #pragma unroll
    for (int i = 0; i < 2; i++)
        #pragma unroll
        for (int j = 0; j < 4; j++)
            #pragma unroll
            for (int e = 0; e < 4; e++) acc[i][j][e] = 0.f;

    // ---- async tile loader: one commit group per chunk
    #define LOAD_TILES(kc)                                                     \
    {                                                                          \
        const uint32_t base = sb + ((kc) % NSTAGE) * BUFB;                     \
        const int ko = (kc) * 32;                                              \
        _Pragma("unroll")                                                      \
        for (int it = 0; it < 2; it++) {                                       \
            int idx = tid + it * 256;                                          \
            int r = idx >> 2, c = idx & 3;                                     \
            uint32_t o = swz(r, c);                                            \
            const char* sh = (const char*)(Abh + (size_t)r * KSTR_A + ko) + c * 16; \
            const char* sl = (const char*)(Abl + (size_t)r * KSTR_A + ko) + c * 16; \
            cpa16(base + OFF_AH + o, sh);                                      \
            cpa16(base + OFF_AL + o, sl);                                      \
        }                                                                      \
        {                                                                      \
            int r = tid >> 2, c = tid & 3;                                     \
            uint32_t o = swz(r, c);                                            \
            const char* sh = (const char*)(Bbh + (size_t)r * KSTR_B + ko) + c * 16; \
            const char* sl = (const char*)(Bbl + (size_t)r * KSTR_B + ko) + c * 16; \
            cpa16(base + OFF_BH + o, sh);                                      \
            cpa16(base + OFF_BL + o, sl);                                      \
        }                                                                      \
        CP_COMMIT();                                                           \
    }

    LOAD_TILES(0);
    LOAD_TILES(1);

    #pragma unroll 1
    for (int kc = 0; kc < KC; kc++) {
        if (kc == KC - 1)
            asm volatile("cp.async.wait_group 0;" ::: "memory");
        else
            asm volatile("cp.async.wait_group 1;" ::: "memory");
        __syncthreads();

        if (kc + 2 < KC) LOAD_TILES(kc + 2);   // into buffer freed last iter

        const uint32_t base = sb + (kc % NSTAGE) * BUFB;
        #pragma unroll
        for (int kk = 0; kk < 2; kk++) {
            uint32_t ah[2][4], al[2][4], bh[4][2], bl[4][2];
            #pragma unroll
            for (int i = 0; i < 2; i++) {
                int row = wm * 32 + i * 16 + (lane & 15);
                int ci  = kk * 2 + (lane >> 4);
                uint32_t ad = base + OFF_AH + swz(row, ci);
                LDM_X4(ah[i], ad);
                LDM_X4(al[i], ad + (OFF_AL - OFF_AH));
            }
            #pragma unroll
            for (int jj = 0; jj < 2; jj++) {
                int row = wn * 32 + jj * 16 + ((lane >> 4) << 3) + (lane & 7);
                int ci  = kk * 2 + ((lane >> 3) & 1);
                uint32_t bd = base + OFF_BH + swz(row, ci);
                uint32_t t[4];
                LDM_X4(t, bd);
                bh[jj*2][0] = t[0]; bh[jj*2][1] = t[1];
                bh[jj*2+1][0] = t[2]; bh[jj*2+1][1] = t[3];
                LDM_X4(t, bd + (OFF_BL - OFF_BH));
                bl[jj*2][0] = t[0]; bl[jj*2][1] = t[1];
                bl[jj*2+1][0] = t[2]; bl[jj*2+1][1] = t[3];
            }
            #pragma unroll
            for (int i = 0; i < 2; i++)
                #pragma unroll
                for (int j = 0; j < 4; j++) MMA_BF16(acc[i][j], ah[i], bh[j]);
            #pragma unroll
            for (int i = 0; i < 2; i++)
                #pragma unroll
                for (int j = 0; j < 4; j++) MMA_BF16(acc[i][j], al[i], bh[j]);
            #pragma unroll
            for (int i = 0; i < 2; i++)
                #pragma unroll
                for (int j = 0; j < 4; j++) MMA_BF16(acc[i][j], ah[i], bl[j]);
        }
    }

    // ---- epilogue
    #pragma unroll
    for (int i = 0; i < 2; i++) {
        int r0 = bm + wm * 32 + i * 16 + (lane >> 2);
        #pragma unroll
        for (int j = 0; j < 4; j++) {
            int col = bn + wn * 32 + j * 8 + (lane & 3) * 2;
            if (SCORES) {
                if (col < 300) {
                    size_t g0 = ((size_t)bz * 1024 + r0) * 300 + col;
                    size_t g1 = g0 + 8 * 300;
                    float2 v0 = make_float2(acc[i][j][0],
                                            (col == 0) ? 0.f : acc[i][j][1]);
                    float2 v1 = make_float2(acc[i][j][2],
                                            (col == 0) ? 0.f : acc[i][j][3]);
                    *(float2*)&outF[g0] = v0;
                    *(float2*)&outF[g1] = v1;
                }
            } else {
                if (col < 224) {
                    uint32_t h, l;
                    size_t p0 = (size_t)r0 * 224 + col;
                    split2(acc[i][j][0], acc[i][j][1], h, l);
                    *(uint32_t*)&Ph[p0] = h; *(uint32_t*)&Pl[p0] = l;
                    size_t p1 = p0 + (size_t)8 * 224;
                    split2(acc[i][j][2], acc[i][j][3], h, l);
                    *(uint32_t*)&Ph[p1] = h; *(uint32_t*)&Pl[p1] = l;
                }
            }
        }
    }
    #undef LOAD_TILES
}

// ------------------------------ launch --------------------------------------
extern "C" void kernel_launch(void* const* d_in, const int* in_sizes, int n_in,
                              void* d_out, int out_size) {
    (void)in_sizes; (void)n_in; (void)out_size;
    const float* roles = (const float*)d_in[0];   // [32, 60000]
    const float* pre   = (const float*)d_in[1];   // [32, 1024, 300]
    const float* wid   = (const float*)d_in[2];   // [32, 1024, 16]
    const float* mat   = (const float*)d_in[3];   // [316, 200]
    float* out = (float*)d_out;                   // [32768, 300]

    cudaFuncSetAttribute(gemm_wmma<320, 320, 10, false>,
                         cudaFuncAttributeMaxDynamicSharedMemorySize, SMEM_TOTAL);
    cudaFuncSetAttribute(gemm_wmma<224, 224, 7, true>,
                         cudaFuncAttributeMaxDynamicSharedMemorySize, SMEM_TOTAL);

    __nv_bfloat16 *a1h, *a1l, *b1h, *b1l, *ph, *pl, *rlh, *rll;
    cudaGetSymbolAddress((void**)&a1h, g_a1h);
    cudaGetSymbolAddress((void**)&a1l, g_a1l);
    cudaGetSymbolAddress((void**)&b1h, g_b1h);
    cudaGetSymbolAddress((void**)&b1l, g_b1l);
    cudaGetSymbolAddress((void**)&ph,  g_ph);
    cudaGetSymbolAddress((void**)&pl,  g_pl);
    cudaGetSymbolAddress((void**)&rlh, g_rlh);
    cudaGetSymbolAddress((void**)&rll, g_rll);

    prep_a1   <<<(32768 * 160 + 255) / 256, 256>>>(pre, wid);
    prep_b1   <<<(256 * 160 + 255) / 256, 256>>>(mat);
    prep_roles<<<(32 * 320 * 112 + 255) / 256, 256>>>(roles);

    // proj: [32768,320] @ b1^T -> g_ph/g_pl stride 224 (4 n-tiles x 256 m-tiles)
    gemm_wmma<320, 320, 10, false><<<dim3(4, 256, 1), 256, SMEM_TOTAL>>>(
        a1h, a1l, b1h, b1l, nullptr, ph, pl);

    // scores: per-batch proj_b @ roles_b^T -> out (5 n-tiles x 8 m-tiles x 32 b)
    gemm_wmma<224, 224, 7, true><<<dim3(5, 8, 32), 256, SMEM_TOTAL>>>(
        ph, pl, rlh, rll, out, nullptr, nullptr);
}

// round 6
// speedup vs baseline: 3.3880x; 1.0104x over previous
#include <cuda_runtime.h>
#include <cuda_bf16.h>
#include <cstdint>

// B=32, S=1024, V=300, PRETRAIN=300, FLAG=16, ROLE_D=200
// Stage 1: proj[32768,224(f32)] = concat(pre,wid)[32768,320] @ matrix^T-tiles
// Stage 2: out[b,1024,300] = proj_b @ roles_b^T, col 1 = 0
//
// Split-bf16 (hi+lo) GEMMs on tensor pipe via mma.sync; the fp32->hi/lo split
// is fused into the GEMM smem loaders (LDG.128 fp32 -> cvt -> STS.128 bf16).
// Only the tiny matrix transpose (prep_b1) remains as a prep kernel.
//   a=ah+al, b=bh+bl; a*b ~= ah*bh + al*bh + ah*bl   (rel err ~1e-5)

// ------------------------------ scratch -------------------------------------
__device__ __align__(16) __nv_bfloat16 g_b1h[256 * 320];
__device__ __align__(16) __nv_bfloat16 g_b1l[256 * 320];
__device__ __align__(16) float         g_p  [32768 * 224];   // fp32 proj

// ------------------------------ helpers -------------------------------------
__device__ __forceinline__ uint32_t smem_u32(const void* p) {
    uint32_t a;
    asm("{ .reg .u64 t; cvta.to.shared.u64 t, %1; cvt.u32.u64 %0, t; }"
        : "=r"(a) : "l"(p));
    return a;
}
#define LDM_X4(r, addr)                                                        \
    asm volatile("ldmatrix.sync.aligned.m8n8.x4.shared.b16 {%0,%1,%2,%3}, [%4];" \
        : "=r"((r)[0]), "=r"((r)[1]), "=r"((r)[2]), "=r"((r)[3]) : "r"(addr))
#define MMA_BF16(d, a, b)                                                      \
    asm volatile("mma.sync.aligned.m16n8k16.row.col.f32.bf16.bf16.f32 "        \
        "{%0,%1,%2,%3}, {%4,%5,%6,%7}, {%8,%9}, {%0,%1,%2,%3};"                \
        : "+f"((d)[0]), "+f"((d)[1]), "+f"((d)[2]), "+f"((d)[3])               \
        : "r"((a)[0]), "r"((a)[1]), "r"((a)[2]), "r"((a)[3]),                  \
          "r"((b)[0]), "r"((b)[1]))

// conflict-free swizzle for 64B rows (4 x 16B granules)
__device__ __forceinline__ uint32_t swz(int r, int c) {
    return (uint32_t)(r * 64 + ((c ^ ((r >> 1) & 3)) << 4));
}

__device__ __forceinline__ uint32_t pk(__nv_bfloat16 x, __nv_bfloat16 y) {
    __nv_bfloat162 p; p.x = x; p.y = y;
    return *(uint32_t*)&p;
}
__device__ __forceinline__ void split2(float x, float y, uint32_t& h, uint32_t& l) {
    __nv_bfloat16 h0 = __float2bfloat16_rn(x);
    __nv_bfloat16 h1 = __float2bfloat16_rn(y);
    __nv_bfloat16 l0 = __float2bfloat16_rn(x - __bfloat162float(h0));
    __nv_bfloat16 l1 = __float2bfloat16_rn(y - __bfloat162float(h1));
    h = pk(h0, h1); l = pk(l0, l1);
}
// 8 fp32 (two float4) -> 16B hi granule + 16B lo granule
__device__ __forceinline__ void split8(float4 u, float4 v, uint4& h, uint4& l) {
    split2(u.x, u.y, h.x, l.x);
    split2(u.z, u.w, h.y, l.y);
    split2(v.x, v.y, h.z, l.z);
    split2(v.z, v.w, h.w, l.w);
}

// ------------------------------ prep (matrix only) --------------------------
__global__ void prep_b1(const float* __restrict__ mat) {
    int idx = blockIdx.x * blockDim.x + threadIdx.x;   // 256*160
    if (idx >= 256 * 160) return;
    int n = idx / 160, kp = idx % 160, k = kp * 2;
    float2 v = make_float2(0.f, 0.f);
    if (n < 200) {
        if (k     < 316) v.x = mat[(k    ) * 200 + n];
        if (k + 1 < 316) v.y = mat[(k + 1) * 200 + n];
    }
    uint32_t h, l; split2(v.x, v.y, h, l);
    ((uint32_t*)g_b1h)[(size_t)n * 160 + kp] = h;
    ((uint32_t*)g_b1l)[(size_t)n * 160 + kp] = l;
}

// ------------------------------ GEMM kernel ---------------------------------
// CTA 128x64, 8 warps (4m x 2n), warp tile 32x32, K-chunk 32.
// smem buffer: Ah[8K] Al[8K] Bh[4K] Bl[4K] = 24KB, double-buffered static.
#define OFF_AH 0
#define OFF_AL 8192
#define OFF_BH 16384
#define OFF_BL 20480
#define BUFB   24576

// PROJ=true : A = concat(pre,wid) fp32 (K=320 eff), B = prepped b1 bf16 pairs.
// PROJ=false: A = g_p fp32 (stride 224),  B = roles fp32 (stride 200, guards).
template <int KC, bool PROJ>
__global__ void __launch_bounds__(256) gemm_fused(
    const float* __restrict__ Afp,        // proj: pre          | scores: g_p
    const float* __restrict__ Awid,       // proj: wid          | unused
    const float* __restrict__ Bfp,        // unused             | scores: roles
    const __nv_bfloat16* __restrict__ B16h,
    const __nv_bfloat16* __restrict__ B16l,
    float* __restrict__ outF,             // unused             | scores: out
    float* __restrict__ Pout)             // proj: g_p          | unused
{
    __shared__ __align__(16) char sm[2][BUFB];
    const uint32_t sb = smem_u32(sm);
    const int tid = threadIdx.x, w = tid >> 5, lane = tid & 31;
    const int wm = w & 3, wn = w >> 2;
    const int bm = blockIdx.y * 128, bn = blockIdx.x * 64, bz = blockIdx.z;

    // task decomposition for loaders
    const int ar0 = tid >> 2, ac0 = tid & 3;            // A task 0: row, granule
    const int ar1 = (tid + 256) >> 2, ac1 = ac0;        // A task 1
    const int br  = tid >> 2, bc = tid & 3;             // B task: row, granule

    float4 pa[4];          // A prefetch: 2 tasks x 2 float4
    float4 pbf[2];         // B prefetch (scores fp32)
    uint4  pbh, pbl;       // B prefetch (proj bf16 pairs)

    float acc[2][4][4];
    #pragma unroll
    for (int i = 0; i < 2; i++)
        #pragma unroll
        for (int j = 0; j < 4; j++)
            #pragma unroll
            for (int e = 0; e < 4; e++) acc[i][j][e] = 0.f;

    // ---- fp32 A gather with source routing -------------------------------
    auto ldA4 = [&](int r, int k) -> float4 {
        if (PROJ) {
            int m = bm + r;
            if (k < 300)      return *(const float4*)&Afp[(size_t)m * 300 + k];
            else if (k < 316) return *(const float4*)&Awid[m * 16 + (k - 300)];
            return make_float4(0.f, 0.f, 0.f, 0.f);
        } else {
            size_t row = (size_t)bz * 1024 + bm + r;
            return *(const float4*)&Afp[row * 224 + k];   // cols<224 all valid
        }
    };
    auto ldB4 = [&](int r, int k) -> float4 {             // scores only
        int v = bn + r;
        if (v < 300 && k < 200)
            return *(const float4*)&Bfp[(size_t)bz * 60000 + (size_t)v * 200 + k];
        return make_float4(0.f, 0.f, 0.f, 0.f);
    };

    #define LOAD_REGS(kc)                                                      \
    {                                                                          \
        const int ko = (kc) * 32;                                              \
        pa[0] = ldA4(ar0, ko + ac0 * 8);                                       \
        pa[1] = ldA4(ar0, ko + ac0 * 8 + 4);                                   \
        pa[2] = ldA4(ar1, ko + ac1 * 8);                                       \
        pa[3] = ldA4(ar1, ko + ac1 * 8 + 4);                                   \
        if (PROJ) {                                                            \
            size_t bo = ((size_t)(bn + br)) * 320 + ko + bc * 8;               \
            pbh = *(const uint4*)&B16h[bo];                                    \
            pbl = *(const uint4*)&B16l[bo];                                    \
        } else {                                                               \
            pbf[0] = ldB4(br, ko + bc * 8);                                    \
            pbf[1] = ldB4(br, ko + bc * 8 + 4);                                \
        }                                                                      \
    }

    #define STORE_SMEM(kc)                                                     \
    {                                                                          \
        const uint32_t base = sb + ((kc) & 1) * BUFB;                          \
        uint4 h, l;                                                            \
        split8(pa[0], pa[1], h, l);                                            \
        *(uint4*)(sm[(kc) & 1] + OFF_AH + swz(ar0, ac0)) = h;                  \
        *(uint4*)(sm[(kc) & 1] + OFF_AL + swz(ar0, ac0)) = l;                  \
        split8(pa[2], pa[3], h, l);                                            \
        *(uint4*)(sm[(kc) & 1] + OFF_AH + swz(ar1, ac1)) = h;                  \
        *(uint4*)(sm[(kc) & 1] + OFF_AL + swz(ar1, ac1)) = l;                  \
        if (PROJ) {                                                            \
            *(uint4*)(sm[(kc) & 1] + OFF_BH + swz(br, bc)) = pbh;              \
            *(uint4*)(sm[(kc) & 1] + OFF_BL + swz(br, bc)) = pbl;              \
        } else {                                                               \
            split8(pbf[0], pbf[1], h, l);                                      \
            *(uint4*)(sm[(kc) & 1] + OFF_BH + swz(br, bc)) = h;                \
            *(uint4*)(sm[(kc) & 1] + OFF_BL + swz(br, bc)) = l;                \
        }                                                                      \
        (void)base;                                                            \
    }

    LOAD_REGS(0);

    #pragma unroll 1
    for (int kc = 0; kc < KC; kc++) {
        STORE_SMEM(kc);
        __syncthreads();
        if (kc + 1 < KC) LOAD_REGS(kc + 1);   // LDGs fly during compute

        const uint32_t base = sb + (kc & 1) * BUFB;
        #pragma unroll
        for (int kk = 0; kk < 2; kk++) {
            uint32_t ah[2][4], al[2][4], bh[4][2], bl[4][2];
            #pragma unroll
            for (int i = 0; i < 2; i++) {
                int row = wm * 32 + i * 16 + (lane & 15);
                int ci  = kk * 2 + (lane >> 4);
                uint32_t ad = base + OFF_AH + swz(row, ci);
                LDM_X4(ah[i], ad);
                LDM_X4(al[i], ad + (OFF_AL - OFF_AH));
            }
            #pragma unroll
            for (int jj = 0; jj < 2; jj++) {
                int row = wn * 32 + jj * 16 + ((lane >> 4) << 3) + (lane & 7);
                int ci  = kk * 2 + ((lane >> 3) & 1);
                uint32_t bd = base + OFF_BH + swz(row, ci);
                uint32_t t[4];
                LDM_X4(t, bd);
                bh[jj*2][0] = t[0]; bh[jj*2][1] = t[1];
                bh[jj*2+1][0] = t[2]; bh[jj*2+1][1] = t[3];
                LDM_X4(t, bd + (OFF_BL - OFF_BH));
                bl[jj*2][0] = t[0]; bl[jj*2][1] = t[1];
                bl[jj*2+1][0] = t[2]; bl[jj*2+1][1] = t[3];
            }
            #pragma unroll
            for (int i = 0; i < 2; i++)
                #pragma unroll
                for (int j = 0; j < 4; j++) MMA_BF16(acc[i][j], ah[i], bh[j]);
            #pragma unroll
            for (int i = 0; i < 2; i++)
                #pragma unroll
                for (int j = 0; j < 4; j++) MMA_BF16(acc[i][j], al[i], bh[j]);
            #pragma unroll
            for (int i = 0; i < 2; i++)
                #pragma unroll
                for (int j = 0; j < 4; j++) MMA_BF16(acc[i][j], ah[i], bl[j]);
        }
        // single sync per chunk: sync at next iter top orders compute(kc)
        // before any STS that reuses this buffer (see safety argument).
    }

    // ---- epilogue
    #pragma unroll
    for (int i = 0; i < 2; i++) {
        int r0 = bm + wm * 32 + i * 16 + (lane >> 2);
        #pragma unroll
        for (int j = 0; j < 4; j++) {
            int col = bn + wn * 32 + j * 8 + (lane & 3) * 2;
            if (PROJ) {
                if (col < 224) {
                    size_t p0 = (size_t)r0 * 224 + col;
                    *(float2*)&Pout[p0] = make_float2(acc[i][j][0], acc[i][j][1]);
                    *(float2*)&Pout[p0 + (size_t)8 * 224] =
                        make_float2(acc[i][j][2], acc[i][j][3]);
                }
            } else {
                if (col < 300) {
                    size_t g0 = ((size_t)bz * 1024 + r0) * 300 + col;
                    *(float2*)&outF[g0] = make_float2(
                        acc[i][j][0], (col == 0) ? 0.f : acc[i][j][1]);
                    *(float2*)&outF[g0 + 8 * 300] = make_float2(
                        acc[i][j][2], (col == 0) ? 0.f : acc[i][j][3]);
                }
            }
        }
    }
    #undef LOAD_REGS
    #undef STORE_SMEM
}

// ------------------------------ launch --------------------------------------
extern "C" void kernel_launch(void* const* d_in, const int* in_sizes, int n_in,
                              void* d_out, int out_size) {
    (void)in_sizes; (void)n_in; (void)out_size;
    const float* roles = (const float*)d_in[0];   // [32, 60000]
    const float* pre   = (const float*)d_in[1];   // [32, 1024, 300]
    const float* wid   = (const float*)d_in[2];   // [32, 1024, 16]
    const float* mat   = (const float*)d_in[3];   // [316, 200]
    float* out = (float*)d_out;                   // [32768, 300]

    __nv_bfloat16 *b1h, *b1l; float* pP;
    cudaGetSymbolAddress((void**)&b1h, g_b1h);
    cudaGetSymbolAddress((void**)&b1l, g_b1l);
    cudaGetSymbolAddress((void**)&pP,  g_p);

    prep_b1<<<(256 * 160 + 255) / 256, 256>>>(mat);

    // proj: fp32 concat(pre,wid) x b1 -> g_p (fp32, stride 224)
    gemm_fused<10, true><<<dim3(4, 256, 1), 256>>>(
        pre, wid, nullptr, b1h, b1l, nullptr, pP);

    // scores: g_p x roles^T -> out
    gemm_fused<7, false><<<dim3(5, 8, 32), 256>>>(
        pP, nullptr, roles, nullptr, nullptr, out, nullptr);
}

// round 7
// speedup vs baseline: 3.5981x; 1.0620x over previous
#include <cuda_runtime.h>
#include <cuda_bf16.h>
#include <cstdint>

// B=32, S=1024, V=300, PRETRAIN=300, FLAG=16, ROLE_D=200
// Stage 1: proj = concat(pre,wid)[32768,316] @ matrix[316,200]
//          (fused A fp32->bf16hi/lo conversion; epilogue stores hi/lo pairs)
// Stage 2: out[b,1024,300] = proj_b @ roles_b^T, col 1 = 0
//          (pure cp.async consumer of prepped hi/lo arrays)
// Split-bf16: a=ah+al, b=bh+bl; a*b ~= ah*bh + al*bh + ah*bl (rel err ~1e-5)

// ------------------------------ scratch -------------------------------------
__device__ __align__(16) __nv_bfloat16 g_b1h[256 * 320];
__device__ __align__(16) __nv_bfloat16 g_b1l[256 * 320];
__device__ __align__(16) __nv_bfloat16 g_ph [32768 * 224];
__device__ __align__(16) __nv_bfloat16 g_pl [32768 * 224];
__device__ __align__(16) __nv_bfloat16 g_rlh[32 * 320 * 224];
__device__ __align__(16) __nv_bfloat16 g_rll[32 * 320 * 224];

// ------------------------------ helpers -------------------------------------
__device__ __forceinline__ uint32_t smem_u32(const void* p) {
    uint32_t a;
    asm("{ .reg .u64 t; cvta.to.shared.u64 t, %1; cvt.u32.u64 %0, t; }"
        : "=r"(a) : "l"(p));
    return a;
}
__device__ __forceinline__ void cpa16(uint32_t dst, const void* src) {
    asm volatile("cp.async.cg.shared.global [%0], [%1], 16;"
                 :: "r"(dst), "l"(src) : "memory");
}
#define CP_COMMIT() asm volatile("cp.async.commit_group;" ::: "memory")
#define LDM_X4(r, addr)                                                        \
    asm volatile("ldmatrix.sync.aligned.m8n8.x4.shared.b16 {%0,%1,%2,%3}, [%4];" \
        : "=r"((r)[0]), "=r"((r)[1]), "=r"((r)[2]), "=r"((r)[3]) : "r"(addr))
#define MMA_BF16(d, a, b)                                                      \
    asm volatile("mma.sync.aligned.m16n8k16.row.col.f32.bf16.bf16.f32 "        \
        "{%0,%1,%2,%3}, {%4,%5,%6,%7}, {%8,%9}, {%0,%1,%2,%3};"                \
        : "+f"((d)[0]), "+f"((d)[1]), "+f"((d)[2]), "+f"((d)[3])               \
        : "r"((a)[0]), "r"((a)[1]), "r"((a)[2]), "r"((a)[3]),                  \
          "r"((b)[0]), "r"((b)[1]))

// conflict-free swizzle for 64B rows (4 x 16B granules)
__device__ __forceinline__ uint32_t swz(int r, int c) {
    return (uint32_t)(r * 64 + ((c ^ ((r >> 1) & 3)) << 4));
}

// Fast split: 6 instructions per 2 elements.
// h = {hi:bf16(y), lo:bf16(x)}; recover hi parts by bit ops; residual -> l.
__device__ __forceinline__ void split2(float x, float y, uint32_t& h, uint32_t& l) {
    asm("cvt.rn.bf16x2.f32 %0, %1, %2;" : "=r"(h) : "f"(y), "f"(x));
    float hx = __uint_as_float(h << 16);
    float hy = __uint_as_float(h & 0xffff0000u);
    float lx = x - hx, ly = y - hy;
    asm("cvt.rn.bf16x2.f32 %0, %1, %2;" : "=r"(l) : "f"(ly), "f"(lx));
}
__device__ __forceinline__ void split8(float4 u, float4 v, uint4& h, uint4& l) {
    split2(u.x, u.y, h.x, l.x);
    split2(u.z, u.w, h.y, l.y);
    split2(v.x, v.y, h.z, l.z);
    split2(v.z, v.w, h.w, l.w);
}

// ------------------------------ prep (roles + matrix, one launch) -----------
#define ROLES_BLOCKS 4480   // 32*320*112 / 256
__global__ void prep_all(const float* __restrict__ roles,
                         const float* __restrict__ mat) {
    int bid = blockIdx.x;
    if (bid < ROLES_BLOCKS) {
        int idx = bid * 256 + threadIdx.x;      // < 32*320*112
        int kp = idx % 112, t = idx / 112;
        int v_ = t % 320, b = t / 320;
        int k = kp * 2;
        float2 v = make_float2(0.f, 0.f);
        if (v_ < 300 && k < 200)
            v = *(const float2*)&roles[(size_t)b * 60000 + (size_t)v_ * 200 + k];
        uint32_t h, l; split2(v.x, v.y, h, l);
        ((uint32_t*)g_rlh)[idx] = h;
        ((uint32_t*)g_rll)[idx] = l;
    } else {
        int idx = (bid - ROLES_BLOCKS) * 256 + threadIdx.x;   // < 256*160
        if (idx < 256 * 160) {
            int n = idx / 160, kp = idx % 160, k = kp * 2;
            float2 v = make_float2(0.f, 0.f);
            if (n < 200) {
                if (k     < 316) v.x = mat[(k    ) * 200 + n];
                if (k + 1 < 316) v.y = mat[(k + 1) * 200 + n];
            }
            uint32_t h, l; split2(v.x, v.y, h, l);
            ((uint32_t*)g_b1h)[idx] = h;
            ((uint32_t*)g_b1l)[idx] = l;
        }
    }
}

// ------------------------------ common tile geometry -------------------------
// CTA 128x64, 8 warps (4m x 2n), warp tile 32x32, K-chunk 32.
#define OFF_AH 0
#define OFF_AL 8192
#define OFF_BH 16384
#define OFF_BL 20480
#define BUFB   24576

// inner compute on one 32-K chunk buffer (shared by both kernels)
#define COMPUTE_CHUNK(base)                                                    \
    _Pragma("unroll")                                                          \
    for (int kk = 0; kk < 2; kk++) {                                           \
        uint32_t ah[2][4], al[2][4], bh[4][2], bl[4][2];                       \
        _Pragma("unroll")                                                      \
        for (int i = 0; i < 2; i++) {                                          \
            int row = wm * 32 + i * 16 + (lane & 15);                          \
            int ci  = kk * 2 + (lane >> 4);                                    \
            uint32_t ad = (base) + OFF_AH + swz(row, ci);                      \
            LDM_X4(ah[i], ad);                                                 \
            LDM_X4(al[i], ad + (OFF_AL - OFF_AH));                             \
        }                                                                      \
        _Pragma("unroll")                                                      \
        for (int jj = 0; jj < 2; jj++) {                                       \
            int row = wn * 32 + jj * 16 + ((lane >> 4) << 3) + (lane & 7);     \
            int ci  = kk * 2 + ((lane >> 3) & 1);                              \
            uint32_t bd = (base) + OFF_BH + swz(row, ci);                      \
            uint32_t t[4];                                                     \
            LDM_X4(t, bd);                                                     \
            bh[jj*2][0] = t[0]; bh[jj*2][1] = t[1];                            \
            bh[jj*2+1][0] = t[2]; bh[jj*2+1][1] = t[3];                        \
            LDM_X4(t, bd + (OFF_BL - OFF_BH));                                 \
            bl[jj*2][0] = t[0]; bl[jj*2][1] = t[1];                            \
            bl[jj*2+1][0] = t[2]; bl[jj*2+1][1] = t[3];                        \
        }                                                                      \
        _Pragma("unroll")                                                      \
        for (int i = 0; i < 2; i++)                                            \
            _Pragma("unroll")                                                  \
            for (int j = 0; j < 4; j++) MMA_BF16(acc[i][j], ah[i], bh[j]);     \
        _Pragma("unroll")                                                      \
        for (int i = 0; i < 2; i++)                                            \
            _Pragma("unroll")                                                  \
            for (int j = 0; j < 4; j++) MMA_BF16(acc[i][j], al[i], bh[j]);     \
        _Pragma("unroll")                                                      \
        for (int i = 0; i < 2; i++)                                            \
            _Pragma("unroll")                                                  \
            for (int j = 0; j < 4; j++) MMA_BF16(acc[i][j], ah[i], bl[j]);     \
    }

// ------------------------------ proj kernel ---------------------------------
// A = fp32 concat(pre,wid), converted in-loader (LDG prefetch, double buffer).
// B = prepped bf16 hi/lo matrix. Epilogue stores proj as bf16 hi/lo, stride 224.
__global__ void __launch_bounds__(256) proj_gemm(
    const float* __restrict__ pre, const float* __restrict__ wid,
    const __nv_bfloat16* __restrict__ B16h, const __nv_bfloat16* __restrict__ B16l,
    __nv_bfloat16* __restrict__ Ph, __nv_bfloat16* __restrict__ Pl)
{
    __shared__ __align__(16) char sm[2][BUFB];
    const int tid = threadIdx.x, w = tid >> 5, lane = tid & 31;
    const int wm = w & 3, wn = w >> 2;
    const int bm = blockIdx.y * 128, bn = blockIdx.x * 64;
    const uint32_t sb = smem_u32(sm);
    const int KC = 10;

    const int ar0 = tid >> 2, ac = tid & 3;
    const int ar1 = ar0 + 64;
    const int br  = tid >> 2, bc = tid & 3;

    float4 pa[4];
    uint4  pbh, pbl;

    float acc[2][4][4];
    #pragma unroll
    for (int i = 0; i < 2; i++)
        #pragma unroll
        for (int j = 0; j < 4; j++)
            #pragma unroll
            for (int e = 0; e < 4; e++) acc[i][j][e] = 0.f;

    auto ldA4 = [&](int r, int k) -> float4 {
        int m = bm + r;
        if (k < 300)      return *(const float4*)&pre[(size_t)m * 300 + k];
        else if (k < 316) return *(const float4*)&wid[m * 16 + (k - 300)];
        return make_float4(0.f, 0.f, 0.f, 0.f);
    };

    #define P_LOAD(kc)                                                         \
    {                                                                          \
        const int ko = (kc) * 32;                                              \
        pa[0] = ldA4(ar0, ko + ac * 8);                                        \
        pa[1] = ldA4(ar0, ko + ac * 8 + 4);                                    \
        pa[2] = ldA4(ar1, ko + ac * 8);                                        \
        pa[3] = ldA4(ar1, ko + ac * 8 + 4);                                    \
        size_t bo = ((size_t)(bn + br)) * 320 + ko + bc * 8;                   \
        pbh = *(const uint4*)&B16h[bo];                                        \
        pbl = *(const uint4*)&B16l[bo];                                        \
    }
    #define P_STORE(kc)                                                        \
    {                                                                          \
        char* bb = sm[(kc) & 1];                                               \
        uint4 h, l;                                                            \
        split8(pa[0], pa[1], h, l);                                            \
        *(uint4*)(bb + OFF_AH + swz(ar0, ac)) = h;                             \
        *(uint4*)(bb + OFF_AL + swz(ar0, ac)) = l;                             \
        split8(pa[2], pa[3], h, l);                                            \
        *(uint4*)(bb + OFF_AH + swz(ar1, ac)) = h;                             \
        *(uint4*)(bb + OFF_AL + swz(ar1, ac)) = l;                             \
        *(uint4*)(bb + OFF_BH + swz(br, bc)) = pbh;                            \
        *(uint4*)(bb + OFF_BL + swz(br, bc)) = pbl;                            \
    }

    P_LOAD(0);
    #pragma unroll 1
    for (int kc = 0; kc < KC; kc++) {
        P_STORE(kc);
        __syncthreads();
        if (kc + 1 < KC) P_LOAD(kc + 1);
        const uint32_t base = sb + (kc & 1) * BUFB;
        COMPUTE_CHUNK(base);
        __syncthreads();   // compute(kc) done before P_STORE reuses buffer
    }

    #pragma unroll
    for (int i = 0; i < 2; i++) {
        int r0 = bm + wm * 32 + i * 16 + (lane >> 2);
        #pragma unroll
        for (int j = 0; j < 4; j++) {
            int col = bn + wn * 32 + j * 8 + (lane & 3) * 2;
            if (col < 224) {
                uint32_t h, l;
                size_t p0 = (size_t)r0 * 224 + col;
                split2(acc[i][j][0], acc[i][j][1], h, l);
                *(uint32_t*)&Ph[p0] = h; *(uint32_t*)&Pl[p0] = l;
                size_t p1 = p0 + (size_t)8 * 224;
                split2(acc[i][j][2], acc[i][j][3], h, l);
                *(uint32_t*)&Ph[p1] = h; *(uint32_t*)&Pl[p1] = l;
            }
        }
    }
    #undef P_LOAD
    #undef P_STORE
}

// ------------------------------ scores kernel --------------------------------
// Pure cp.async consumer: A = g_ph/g_pl, B = g_rlh/g_rll (both stride 224).
#define NSTAGE 3
#define SC_SMEM (NSTAGE * BUFB)

__global__ void __launch_bounds__(256) scores_gemm(
    const __nv_bfloat16* __restrict__ Agh, const __nv_bfloat16* __restrict__ Agl,
    const __nv_bfloat16* __restrict__ Bgh, const __nv_bfloat16* __restrict__ Bgl,
    float* __restrict__ outF)
{
    extern __shared__ __align__(16) char smem_dyn[];
    const uint32_t sb = smem_u32(smem_dyn);
    const int tid = threadIdx.x, w = tid >> 5, lane = tid & 31;
    const int wm = w & 3, wn = w >> 2;
    const int bm = blockIdx.y * 128, bn = blockIdx.x * 64, bz = blockIdx.z;
    const int KC = 7;

    size_t ao = ((size_t)bz * 1024 + bm) * 224;
    size_t bo = ((size_t)bz * 320 + bn) * 224;
    const __nv_bfloat16* Abh = Agh + ao;
    const __nv_bfloat16* Abl = Agl + ao;
    const __nv_bfloat16* Bbh = Bgh + bo;
    const __nv_bfloat16* Bbl = Bgl + bo;

    float acc[2][4][4];
    #pragma unroll
    for (int i = 0; i < 2; i++)
        #pragma unroll
        for (int j = 0; j < 4; j++)
            #pragma unroll
            for (int e = 0; e < 4; e++) acc[i][j][e] = 0.f;

    #define S_LOAD(kc)                                                         \
    {                                                                          \
        const uint32_t base = sb + ((kc) % NSTAGE) * BUFB;                     \
        const int ko = (kc) * 32;                                              \
        _Pragma("unroll")                                                      \
        for (int it = 0; it < 2; it++) {                                       \
            int idx = tid + it * 256;                                          \
            int r = idx >> 2, c = idx & 3;                                     \
            uint32_t o = swz(r, c);                                            \
            const char* sh = (const char*)(Abh + (size_t)r * 224 + ko) + c * 16; \
            const char* sl = (const char*)(Abl + (size_t)r * 224 + ko) + c * 16; \
            cpa16(base + OFF_AH + o, sh);                                      \
            cpa16(base + OFF_AL + o, sl);                                      \
        }                                                                      \
        {                                                                      \
            int r = tid >> 2, c = tid & 3;                                     \
            uint32_t o = swz(r, c);                                            \
            const char* sh = (const char*)(Bbh + (size_t)r * 224 + ko) + c * 16; \
            const char* sl = (const char*)(Bbl + (size_t)r * 224 + ko) + c * 16; \
            cpa16(base + OFF_BH + o, sh);                                      \
            cpa16(base + OFF_BL + o, sl);                                      \
        }                                                                      \
        CP_COMMIT();                                                           \
    }

    S_LOAD(0);
    S_LOAD(1);

    #pragma unroll 1
    for (int kc = 0; kc < KC; kc++) {
        if (kc == KC - 1)
            asm volatile("cp.async.wait_group 0;" ::: "memory");
        else
            asm volatile("cp.async.wait_group 1;" ::: "memory");
        __syncthreads();
        if (kc + 2 < KC) S_LOAD(kc + 2);
        const uint32_t base = sb + (kc % NSTAGE) * BUFB;
        COMPUTE_CHUNK(base);
    }

    #pragma unroll
    for (int i = 0; i < 2; i++) {
        int r0 = bm + wm * 32 + i * 16 + (lane >> 2);
        #pragma unroll
        for (int j = 0; j < 4; j++) {
            int col = bn + wn * 32 + j * 8 + (lane & 3) * 2;
            if (col < 300) {
                size_t g0 = ((size_t)bz * 1024 + r0) * 300 + col;
                *(float2*)&outF[g0] = make_float2(
                    acc[i][j][0], (col == 0) ? 0.f : acc[i][j][1]);
                *(float2*)&outF[g0 + 8 * 300] = make_float2(
                    acc[i][j][2], (col == 0) ? 0.f : acc[i][j][3]);
            }
        }
    }
    #undef S_LOAD
}

// ------------------------------ launch --------------------------------------
extern "C" void kernel_launch(void* const* d_in, const int* in_sizes, int n_in,
                              void* d_out, int out_size) {
    (void)in_sizes; (void)n_in; (void)out_size;
    const float* roles = (const float*)d_in[0];   // [32, 60000]
    const float* pre   = (const float*)d_in[1];   // [32, 1024, 300]
    const float* wid   = (const float*)d_in[2];   // [32, 1024, 16]
    const float* mat   = (const float*)d_in[3];   // [316, 200]
    float* out = (float*)d_out;                   // [32768, 300]

    cudaFuncSetAttribute(scores_gemm,
                         cudaFuncAttributeMaxDynamicSharedMemorySize, SC_SMEM);

    __nv_bfloat16 *b1h, *b1l, *ph, *pl, *rlh, *rll;
    cudaGetSymbolAddress((void**)&b1h, g_b1h);
    cudaGetSymbolAddress((void**)&b1l, g_b1l);
    cudaGetSymbolAddress((void**)&ph,  g_ph);
    cudaGetSymbolAddress((void**)&pl,  g_pl);
    cudaGetSymbolAddress((void**)&rlh, g_rlh);
    cudaGetSymbolAddress((void**)&rll, g_rll);

    prep_all<<<ROLES_BLOCKS + 160, 256>>>(roles, mat);

    // proj: fp32 inputs x prepped matrix -> hi/lo proj (stride 224)
    proj_gemm<<<dim3(4, 256, 1), 256>>>(pre, wid, b1h, b1l, ph, pl);

    // scores: prepped proj x prepped roles -> out
    scores_gemm<<<dim3(5, 8, 32), 256, SC_SMEM>>>(ph, pl, rlh, rll, out);
}